// round 14
// baseline (speedup 1.0000x reference)
#include <cuda_runtime.h>
#include <cuda_fp16.h>
#include <math.h>
#include <stdint.h>

#define SEQ 4096
#define DMODEL 1024
#define DQKV 3072

// Scratch (allocation-free rule: __device__ globals)
__device__ __half g_Eh[(size_t)SEQ * DMODEL];     // fp16 E          [4096,1024]
__device__ __half g_Wh[(size_t)3 * DMODEL * DMODEL]; // fp16 Wq|Wk|Wv (each [in,out], NOT transposed)
__device__ __half g_QKVh[(size_t)SEQ * DQKV];     // fp16 Q|K|V      [4096,3072]
__device__ __half g_Sh[(size_t)SEQ * SEQ];        // fp16 scores -> probs (in place)

// ---------------------------------------------------------------------------
// helpers
// ---------------------------------------------------------------------------
__device__ __forceinline__ void cpa16(void* s, const void* g) {
    uint32_t sa = (uint32_t)__cvta_generic_to_shared(s);
    asm volatile("cp.async.cg.shared.global [%0], [%1], 16;" :: "r"(sa), "l"(g));
}
__device__ __forceinline__ void cpa_commit() { asm volatile("cp.async.commit_group;"); }
template <int N>
__device__ __forceinline__ void cpa_wait() { asm volatile("cp.async.wait_group %0;" :: "n"(N)); }

__device__ __forceinline__ void ldsm_x4(uint32_t addr, uint32_t r[4]) {
    asm volatile("ldmatrix.sync.aligned.m8n8.x4.shared.b16 {%0,%1,%2,%3}, [%4];"
                 : "=r"(r[0]), "=r"(r[1]), "=r"(r[2]), "=r"(r[3]) : "r"(addr));
}
__device__ __forceinline__ void ldsm_x4_t(uint32_t addr, uint32_t r[4]) {
    asm volatile("ldmatrix.sync.aligned.m8n8.x4.trans.shared.b16 {%0,%1,%2,%3}, [%4];"
                 : "=r"(r[0]), "=r"(r[1]), "=r"(r[2]), "=r"(r[3]) : "r"(addr));
}

__device__ __forceinline__ void mma_f16(float c[4], const uint32_t a[4], const uint32_t b[2]) {
    asm volatile(
        "mma.sync.aligned.m16n8k16.row.col.f32.f16.f16.f32 "
        "{%0,%1,%2,%3}, {%4,%5,%6,%7}, {%8,%9}, {%0,%1,%2,%3};"
        : "+f"(c[0]), "+f"(c[1]), "+f"(c[2]), "+f"(c[3])
        : "r"(a[0]), "r"(a[1]), "r"(a[2]), "r"(a[3]), "r"(b[0]), "r"(b[1]));
}

__device__ __forceinline__ void st2(float* p, float x, float y) {
    *(float2*)p = make_float2(x, y);
}
__device__ __forceinline__ void st2(__half* p, float x, float y) {
    *(__half2*)p = __floats2half2_rn(x, y);
}

// ---------------------------------------------------------------------------
// Prepass: fp32 -> fp16 for E (4 x 1M chunks) and Wq/Wk/Wv (1M each), one launch.
// grid = (1024, 1, 7); each z handles one 1M-element chunk (262144 float4s).
// ---------------------------------------------------------------------------
__global__ void f2h_all(const float* __restrict__ E,
                        const float* __restrict__ Wq,
                        const float* __restrict__ Wk,
                        const float* __restrict__ Wv,
                        __half* __restrict__ Eh, __half* __restrict__ Wh)
{
    const int z = blockIdx.z;
    const size_t MM = (size_t)DMODEL * DMODEL;   // 1M elements
    const float* src;
    __half* dst;
    if (z < 4)      { src = E  + (size_t)z * MM;       dst = Eh + (size_t)z * MM; }
    else if (z == 4){ src = Wq;                         dst = Wh; }
    else if (z == 5){ src = Wk;                         dst = Wh + MM; }
    else            { src = Wv;                         dst = Wh + 2 * MM; }

    int i = blockIdx.x * blockDim.x + threadIdx.x;   // float4 index, 0..262143
    float4 v = ((const float4*)src)[i];
    ((__half2*)dst)[2 * i + 0] = __floats2half2_rn(v.x, v.y);
    ((__half2*)dst)[2 * i + 1] = __floats2half2_rn(v.z, v.w);
}

// ---------------------------------------------------------------------------
// FP16 mma.sync GEMM, CTA tile 128x128, K-tile 64, 128 threads / 4 warps,
// warp tile 64x64, fp32 accumulate, fragment + cp.async double buffering.
//   BTRANS=false (NT): B is [N,K] row-major (K-major)  -> plain ldmatrix
//   BTRANS=true  (NN): B is [K,N] row-major (N-major)  -> ldmatrix.trans
// NN supports banded B (3 separate matrices along N, band_shift = log2 tiles
// per band); NT uses B0 only. A always [M,K] K-major fp16.
// ---------------------------------------------------------------------------
template <typename OutT, bool BTRANS>
__global__ __launch_bounds__(128, 2)
void hgemm(const __half* __restrict__ A, int lda,
           const __half* __restrict__ B0, const __half* __restrict__ B1,
           const __half* __restrict__ B2, int band_shift, int ldb,
           OutT* __restrict__ C, int ldc,
           int K, float alpha)
{
    extern __shared__ char smem[];
    const uint32_t sbase = (uint32_t)__cvta_generic_to_shared(smem);

    const int tid  = threadIdx.x;
    const int lane = tid & 31;
    const int wid  = tid >> 5;
    const int warp_m = (wid & 1) * 64;
    const int warp_n = (wid >> 1) * 64;
    const int bx = blockIdx.x, by = blockIdx.y;
    const int NT = K / 64;

    const int band = bx >> band_shift;
    const int bxl  = bx & ((1 << band_shift) - 1);
    const __half* Bp = (band == 0) ? B0 : (band == 1) ? B1 : B2;

    const __half* Arow = A + (size_t)(by * 128) * lda;
    const __half* Brow = BTRANS ? (Bp + bxl * 128)                     // col offset
                                : (Bp + (size_t)(bxl * 128) * ldb);    // row offset

    // stage = 32KB: A tile 16KB (128 rows x 128B) | B tile 16KB
    //   NT: 128 n-rows x 128B ;  NN: 64 k-rows x 256B
    auto load_tile = [&](int buf, int kt) {
        const int k0 = kt * 64;
        char* st = smem + buf * 32768;
        #pragma unroll
        for (int l = 0; l < 8; l++) {
            int c = tid + l * 128;
            int row = c >> 3, ch = c & 7;
            uint32_t off = (uint32_t)(row * 128 + ((ch * 16) ^ ((row & 7) << 4)));
            cpa16(st + off, Arow + (size_t)row * lda + k0 + ch * 8);
        }
        if (!BTRANS) {
            #pragma unroll
            for (int l = 0; l < 8; l++) {
                int c = tid + l * 128;
                int row = c >> 3, ch = c & 7;
                uint32_t off = (uint32_t)(row * 128 + ((ch * 16) ^ ((row & 7) << 4)));
                cpa16(st + 16384 + off, Brow + (size_t)row * ldb + k0 + ch * 8);
            }
        } else {
            #pragma unroll
            for (int l = 0; l < 8; l++) {
                int c = tid + l * 128;
                int row = c >> 4, ch = c & 15;       // 64 rows x 16 chunks
                uint32_t off = (uint32_t)(row * 256 + ((ch * 16) ^ ((row & 7) << 4)));
                cpa16(st + 16384 + off, Brow + (size_t)(k0 + row) * ldb + ch * 8);
            }
        }
        cpa_commit();
    };

    // ---- per-lane fragment addressing ----
    const uint32_t xmask = (uint32_t)((lane & 7) << 4);
    // A quadrants: {m0,k0},{m8,k0},{m0,k8},{m8,k8}
    const int a_row = warp_m + (lane & 7) + ((lane >> 3) & 1) * 8;
    const uint32_t a_kh = (uint32_t)((lane >> 4) * 16);
    const uint32_t a_base = sbase + (uint32_t)(a_row * 128);

    // NT B quadrants: {n0,k0},{n0,k8},{n8,k0},{n8,k8}
    const int b_row = warp_n + (lane & 7) + ((lane >> 4) & 1) * 8;
    const uint32_t b_kh = (uint32_t)(((lane >> 3) & 1) * 16);
    const uint32_t b_base = sbase + 16384u + (uint32_t)(b_row * 128);

    // NN B quadrants (trans): j=lane>>3: {k0,n0},{k8,n0},{k0,n8},{k8,n8}
    const int jq = lane >> 3;
    const int nn_row = (jq & 1) * 8 + (lane & 7);            // k within 16-block
    const uint32_t nn_nb = (uint32_t)(warp_n * 2 + ((jq >> 1) & 1) * 16);
    const uint32_t bnn_base = sbase + 16384u + (uint32_t)(nn_row * 256);

    auto lfrag = [&](uint32_t soff, int ks, uint32_t a[4][4], uint32_t b[4][4]) {
        const uint32_t ka = ((uint32_t)(ks * 32) + a_kh) ^ xmask;
        #pragma unroll
        for (int mf = 0; mf < 4; mf++)
            ldsm_x4(a_base + soff + (uint32_t)(mf * 2048) + ka, a[mf]);
        if (!BTRANS) {
            const uint32_t kb = ((uint32_t)(ks * 32) + b_kh) ^ xmask;
            #pragma unroll
            for (int pr = 0; pr < 4; pr++)
                ldsm_x4(b_base + soff + (uint32_t)(pr * 2048) + kb, b[pr]);
        } else {
            #pragma unroll
            for (int pr = 0; pr < 4; pr++) {
                uint32_t addr = bnn_base + soff + (uint32_t)(ks * 4096)
                              + ((nn_nb + (uint32_t)(pr * 32)) ^ xmask);
                ldsm_x4_t(addr, b[pr]);
            }
        }
    };

    float acc[4][8][4];
    #pragma unroll
    for (int i = 0; i < 4; i++)
        #pragma unroll
        for (int j = 0; j < 8; j++)
            #pragma unroll
            for (int r = 0; r < 4; r++) acc[i][j][r] = 0.f;

    load_tile(0, 0);
    if (NT > 1) load_tile(1, 1);

    for (int kt = 0; kt < NT; kt++) {
        if (kt + 1 < NT) cpa_wait<1>(); else cpa_wait<0>();
        __syncthreads();
        if (kt + 2 < NT) load_tile((kt + 2) % 3, kt + 2);

        const uint32_t soff = (uint32_t)((kt % 3) * 32768);

        uint32_t a[2][4][4];
        uint32_t b[2][4][4];
        lfrag(soff, 0, a[0], b[0]);

        #pragma unroll
        for (int ks = 0; ks < 4; ks++) {
            if (ks < 3) lfrag(soff, ks + 1, a[(ks + 1) & 1], b[(ks + 1) & 1]);
            const uint32_t (*ac)[4] = a[ks & 1];
            const uint32_t (*bc)[4] = b[ks & 1];
            #pragma unroll
            for (int mf = 0; mf < 4; mf++)
                #pragma unroll
                for (int nf = 0; nf < 8; nf++)
                    mma_f16(acc[mf][nf], ac[mf], &bc[nf >> 1][(nf & 1) * 2]);
        }
    }

    // ---- epilogue ----
    const int crow = by * 128 + warp_m + (lane >> 2);
    const int ccol = bx * 128 + warp_n + ((lane & 3) << 1);
    #pragma unroll
    for (int mf = 0; mf < 4; mf++) {
        #pragma unroll
        for (int nf = 0; nf < 8; nf++) {
            st2(C + (size_t)(crow + mf * 16)     * ldc + ccol + nf * 8,
                acc[mf][nf][0] * alpha, acc[mf][nf][1] * alpha);
            st2(C + (size_t)(crow + mf * 16 + 8) * ldc + ccol + nf * 8,
                acc[mf][nf][2] * alpha, acc[mf][nf][3] * alpha);
        }
    }
}

// ---------------------------------------------------------------------------
// Row softmax over fp16 S[SEQ][SEQ], in place (probs overwrite scores).
// One block per row, 256 threads, fp32 math.
// ---------------------------------------------------------------------------
__global__ __launch_bounds__(256)
void softmax_h(__half* __restrict__ S)
{
    constexpr int T = 256;
    constexpr int NV = SEQ / 2 / T;      // 8 half2 per thread
    __shared__ float red[8];
    __shared__ float bcast;

    const int tid = threadIdx.x;
    __half2* p = (__half2*)(S + (size_t)blockIdx.x * SEQ);

    float2 v[NV];
    float mx = -INFINITY;
    #pragma unroll
    for (int i = 0; i < NV; i++) {
        v[i] = __half22float2(p[tid + i * T]);
        mx = fmaxf(mx, fmaxf(v[i].x, v[i].y));
    }
    #pragma unroll
    for (int o = 16; o; o >>= 1) mx = fmaxf(mx, __shfl_xor_sync(0xffffffffu, mx, o));
    if ((tid & 31) == 0) red[tid >> 5] = mx;
    __syncthreads();
    if (tid == 0) {
        float m = red[0];
        #pragma unroll
        for (int i = 1; i < 8; i++) m = fmaxf(m, red[i]);
        bcast = m;
    }
    __syncthreads();
    mx = bcast;

    float sum = 0.f;
    #pragma unroll
    for (int i = 0; i < NV; i++) {
        v[i].x = __expf(v[i].x - mx);
        v[i].y = __expf(v[i].y - mx);
        sum += v[i].x + v[i].y;
    }
    #pragma unroll
    for (int o = 16; o; o >>= 1) sum += __shfl_xor_sync(0xffffffffu, sum, o);
    __syncthreads();
    if ((tid & 31) == 0) red[tid >> 5] = sum;
    __syncthreads();
    if (tid == 0) {
        float s = 0.f;
        #pragma unroll
        for (int i = 0; i < 8; i++) s += red[i];
        bcast = 1.f / s;
    }
    __syncthreads();
    const float inv = bcast;

    #pragma unroll
    for (int i = 0; i < NV; i++)
        p[tid + i * T] = __floats2half2_rn(v[i].x * inv, v[i].y * inv);
}

// ---------------------------------------------------------------------------
extern "C" void kernel_launch(void* const* d_in, const int* in_sizes, int n_in,
                              void* d_out, int out_size)
{
    const float* E  = (const float*)d_in[0];
    const float* Wq = (const float*)d_in[1];
    const float* Wk = (const float*)d_in[2];
    const float* Wv = (const float*)d_in[3];
    float* out = (float*)d_out;

    __half *Eh, *Wh, *QKVh, *Sh;
    cudaGetSymbolAddress((void**)&Eh,   g_Eh);
    cudaGetSymbolAddress((void**)&Wh,   g_Wh);
    cudaGetSymbolAddress((void**)&QKVh, g_QKVh);
    cudaGetSymbolAddress((void**)&Sh,   g_Sh);

    constexpr int SMEM_BYTES = 3 * 32768;   // 98304
    cudaFuncSetAttribute(hgemm<__half, true>,
                         cudaFuncAttributeMaxDynamicSharedMemorySize, SMEM_BYTES);
    cudaFuncSetAttribute(hgemm<__half, false>,
                         cudaFuncAttributeMaxDynamicSharedMemorySize, SMEM_BYTES);
    cudaFuncSetAttribute(hgemm<float, true>,
                         cudaFuncAttributeMaxDynamicSharedMemorySize, SMEM_BYTES);

    const size_t MM = (size_t)DMODEL * DMODEL;

    // prepass: E + Wq/Wk/Wv -> fp16, one launch
    f2h_all<<<dim3(1024, 1, 7), 256>>>(E, Wq, Wk, Wv, Eh, Wh);

    dim3 blk(128);

    // QKV: [4096,3072] = E @ [Wq|Wk|Wv]  (NN, banded B: 8 tiles per W)
    hgemm<__half, true><<<dim3(DQKV / 128, SEQ / 128), blk, SMEM_BYTES>>>(
        Eh, DMODEL, Wh, Wh + MM, Wh + 2 * MM, 3, DMODEL,
        QKVh, DQKV, DMODEL, 1.0f);

    const __half* Q  = QKVh;
    const __half* Kp = QKVh + DMODEL;
    const __half* V  = QKVh + 2 * DMODEL;

    // S = (Q @ K^T) / 32  (NT), fp16 out
    hgemm<__half, false><<<dim3(SEQ / 128, SEQ / 128), blk, SMEM_BYTES>>>(
        Q, DQKV, Kp, Kp, Kp, 30, DQKV,
        Sh, SEQ, DMODEL, 0.03125f);

    // softmax in place (S -> P, fp16)
    softmax_h<<<SEQ, 256>>>(Sh);

    // out = P @ V  (NN: V consumed directly from QKV buffer), fp32 out
    hgemm<float, true><<<dim3(DMODEL / 128, SEQ / 128), blk, SMEM_BYTES>>>(
        Sh, SEQ, V, V, V, 30, DQKV,
        out, DMODEL, SEQ, 1.0f);
}

// round 17
// speedup vs baseline: 1.0142x; 1.0142x over previous
#include <cuda_runtime.h>
#include <cuda_fp16.h>
#include <math.h>
#include <stdint.h>

#define SEQ 4096
#define DMODEL 1024
#define DQKV 3072

// Scratch (allocation-free rule: __device__ globals)
__device__ __half g_Eh[(size_t)SEQ * DMODEL];     // fp16 E            [4096,1024]
__device__ __half g_Wh[(size_t)DQKV * DMODEL];    // fp16 W^T          [3072,1024] (n,k)
__device__ __half g_QKVh[(size_t)SEQ * DQKV];     // fp16 Q|K|V        [4096,3072]
__device__ __half g_Vth[(size_t)DMODEL * SEQ];    // fp16 V^T          [1024,4096]
__device__ __half g_Sh[(size_t)SEQ * SEQ];        // fp16 scores -> probs (in place)

// ---------------------------------------------------------------------------
// helpers
// ---------------------------------------------------------------------------
__device__ __forceinline__ void cpa16(void* s, const void* g) {
    uint32_t sa = (uint32_t)__cvta_generic_to_shared(s);
    asm volatile("cp.async.cg.shared.global [%0], [%1], 16;" :: "r"(sa), "l"(g));
}
__device__ __forceinline__ void cpa_commit() { asm volatile("cp.async.commit_group;"); }
template <int N>
__device__ __forceinline__ void cpa_wait() { asm volatile("cp.async.wait_group %0;" :: "n"(N)); }

__device__ __forceinline__ void ldsm_x4(uint32_t addr, uint32_t r[4]) {
    asm volatile("ldmatrix.sync.aligned.m8n8.x4.shared.b16 {%0,%1,%2,%3}, [%4];"
                 : "=r"(r[0]), "=r"(r[1]), "=r"(r[2]), "=r"(r[3]) : "r"(addr));
}

__device__ __forceinline__ void mma_f16(float c[4], const uint32_t a[4], const uint32_t b[2]) {
    asm volatile(
        "mma.sync.aligned.m16n8k16.row.col.f32.f16.f16.f32 "
        "{%0,%1,%2,%3}, {%4,%5,%6,%7}, {%8,%9}, {%0,%1,%2,%3};"
        : "+f"(c[0]), "+f"(c[1]), "+f"(c[2]), "+f"(c[3])
        : "r"(a[0]), "r"(a[1]), "r"(a[2]), "r"(a[3]), "r"(b[0]), "r"(b[1]));
}

// paired store: fp32 or fp16 (rounds here)
__device__ __forceinline__ void st2(float* p, float x, float y) {
    *(float2*)p = make_float2(x, y);
}
__device__ __forceinline__ void st2(__half* p, float x, float y) {
    *(__half2*)p = __floats2half2_rn(x, y);
}

// ---------------------------------------------------------------------------
// Prepass: E fp32 -> fp16 (4 x 1M chunks via z)
// ---------------------------------------------------------------------------
__global__ void f2h_e(const float* __restrict__ E, __half* __restrict__ Eh)
{
    const size_t MM = (size_t)DMODEL * DMODEL;
    const float* src = E + (size_t)blockIdx.z * MM;
    __half* dst = Eh + (size_t)blockIdx.z * MM;
    int i = blockIdx.x * blockDim.x + threadIdx.x;
    float4 v = ((const float4*)src)[i];
    ((__half2*)dst)[2 * i + 0] = __floats2half2_rn(v.x, v.y);
    ((__half2*)dst)[2 * i + 1] = __floats2half2_rn(v.z, v.w);
}

// Merged W transpose: z selects Wq/Wk/Wv; fp32 in -> fp16 out (transposed).
__global__ __launch_bounds__(256)
void transpose_w3(const float* __restrict__ w0, const float* __restrict__ w1,
                  const float* __restrict__ w2, __half* __restrict__ dst)
{
    __shared__ float t[32][33];
    const int tx = threadIdx.x & 7;
    const int ty = threadIdx.x >> 3;
    const int r0 = blockIdx.y * 32, c0 = blockIdx.x * 32;
    const float* src = (blockIdx.z == 0) ? w0 : (blockIdx.z == 1) ? w1 : w2;
    __half* d = dst + (size_t)blockIdx.z * DMODEL * DMODEL;

    float4 v = *(const float4*)(src + (size_t)(r0 + ty) * DMODEL + c0 + tx * 4);
    t[ty][tx * 4 + 0] = v.x; t[ty][tx * 4 + 1] = v.y;
    t[ty][tx * 4 + 2] = v.z; t[ty][tx * 4 + 3] = v.w;
    __syncthreads();

    __half* o = d + (size_t)(c0 + ty) * DMODEL + r0 + tx * 4;
    *(__half2*)(o + 0) = __floats2half2_rn(t[tx * 4 + 0][ty], t[tx * 4 + 1][ty]);
    *(__half2*)(o + 2) = __floats2half2_rn(t[tx * 4 + 2][ty], t[tx * 4 + 3][ty]);
}

// fp16 transpose: src[R,C] (ld=lds) -> dst[C,R] (ld=ldd)
__global__ __launch_bounds__(256)
void transpose_h(const __half* __restrict__ src, int lds,
                 __half* __restrict__ dst, int ldd)
{
    __shared__ float t[32][33];
    const int tx = threadIdx.x & 7;
    const int ty = threadIdx.x >> 3;
    const int r0 = blockIdx.y * 32, c0 = blockIdx.x * 32;

    const __half* s = src + (size_t)(r0 + ty) * lds + c0 + tx * 4;
    __half2 h0 = *(const __half2*)(s + 0);
    __half2 h1 = *(const __half2*)(s + 2);
    t[ty][tx * 4 + 0] = __low2float(h0);  t[ty][tx * 4 + 1] = __high2float(h0);
    t[ty][tx * 4 + 2] = __low2float(h1);  t[ty][tx * 4 + 3] = __high2float(h1);
    __syncthreads();

    __half* o = dst + (size_t)(c0 + ty) * ldd + r0 + tx * 4;
    *(__half2*)(o + 0) = __floats2half2_rn(t[tx * 4 + 0][ty], t[tx * 4 + 1][ty]);
    *(__half2*)(o + 2) = __floats2half2_rn(t[tx * 4 + 2][ty], t[tx * 4 + 3][ty]);
}

// ---------------------------------------------------------------------------
// FP16 mma.sync GEMM (NT): C[M,N] = alpha * A[M,K] @ B[N,K]^T.
// A,B fp16 row-major K-major; C fp32 or fp16 (OutT). fp32 accumulate.
// CTA tile 128x128, K-tile 64 halves (128B SW-swizzled rows). 128 threads /
// 4 warps, warp tile 64x64, m16n8k16 fragments via ldmatrix.x4.
// 3-stage cp.async pipeline, fragment double-buffering across k16-steps.
// (This is the R12-measured mainloop, unchanged.)
// ---------------------------------------------------------------------------
template <typename OutT>
__global__ __launch_bounds__(128, 2)
void hgemm(const __half* __restrict__ A, int lda,
           const __half* __restrict__ B, int ldb,
           OutT* __restrict__ C, int ldc,
           int K, float alpha)
{
    extern __shared__ char smem[];
    const uint32_t sbase = (uint32_t)__cvta_generic_to_shared(smem);

    const int tid  = threadIdx.x;
    const int lane = tid & 31;
    const int wid  = tid >> 5;           // 0..3
    const int warp_m = (wid & 1) * 64;
    const int warp_n = (wid >> 1) * 64;
    const int bx = blockIdx.x, by = blockIdx.y;
    const int NT = K / 64;

    const __half* Arow = A + (size_t)(by * 128) * lda;
    const __half* Brow = B + (size_t)(bx * 128) * ldb;

    // stage = 32KB: A tile 16KB (128 rows x 128B = 64 halves) | B tile 16KB
    auto load_tile = [&](int buf, int kt) {
        const int k0 = kt * 64;
        char* st = smem + buf * 32768;
        #pragma unroll
        for (int l = 0; l < 8; l++) {
            int c = tid + l * 128;
            int row = c >> 3, ch = c & 7;
            uint32_t off = (uint32_t)(row * 128 + ((ch * 16) ^ ((row & 7) << 4)));
            cpa16(st + off, Arow + (size_t)row * lda + k0 + ch * 8);
        }
        #pragma unroll
        for (int l = 0; l < 8; l++) {
            int c = tid + l * 128;
            int row = c >> 3, ch = c & 7;
            uint32_t off = (uint32_t)(row * 128 + ((ch * 16) ^ ((row & 7) << 4)));
            cpa16(st + 16384 + off, Brow + (size_t)row * ldb + k0 + ch * 8);
        }
        cpa_commit();
    };

    const uint32_t xmask = (uint32_t)((lane & 7) << 4);
    // A quadrants: {m0,k0},{m8,k0},{m0,k8},{m8,k8}
    const int a_row = warp_m + (lane & 7) + ((lane >> 3) & 1) * 8;
    const uint32_t a_kh = (uint32_t)((lane >> 4) * 16);
    // B quadrants: {n0,k0},{n0,k8},{n8,k0},{n8,k8}
    const int b_row = warp_n + (lane & 7) + ((lane >> 4) & 1) * 8;
    const uint32_t b_kh = (uint32_t)(((lane >> 3) & 1) * 16);

    const uint32_t a_base = sbase + (uint32_t)(a_row * 128);
    const uint32_t b_base = sbase + 16384u + (uint32_t)(b_row * 128);

    auto lfrag = [&](uint32_t soff, int ks, uint32_t a[4][4], uint32_t b[4][4]) {
        const uint32_t ka = ((uint32_t)(ks * 32) + a_kh) ^ xmask;
        const uint32_t kb = ((uint32_t)(ks * 32) + b_kh) ^ xmask;
        #pragma unroll
        for (int mf = 0; mf < 4; mf++)
            ldsm_x4(a_base + soff + (uint32_t)(mf * 2048) + ka, a[mf]);
        #pragma unroll
        for (int pr = 0; pr < 4; pr++)
            ldsm_x4(b_base + soff + (uint32_t)(pr * 2048) + kb, b[pr]);
    };

    float acc[4][8][4];
    #pragma unroll
    for (int i = 0; i < 4; i++)
        #pragma unroll
        for (int j = 0; j < 8; j++)
            #pragma unroll
            for (int r = 0; r < 4; r++) acc[i][j][r] = 0.f;

    load_tile(0, 0);
    if (NT > 1) load_tile(1, 1);

    for (int kt = 0; kt < NT; kt++) {
        if (kt + 1 < NT) cpa_wait<1>(); else cpa_wait<0>();
        __syncthreads();
        if (kt + 2 < NT) load_tile((kt + 2) % 3, kt + 2);

        const uint32_t soff = (uint32_t)((kt % 3) * 32768);

        uint32_t a[2][4][4];
        uint32_t b[2][4][4];
        lfrag(soff, 0, a[0], b[0]);

        #pragma unroll
        for (int ks = 0; ks < 4; ks++) {
            if (ks < 3) lfrag(soff, ks + 1, a[(ks + 1) & 1], b[(ks + 1) & 1]);
            const uint32_t (*ac)[4] = a[ks & 1];
            const uint32_t (*bc)[4] = b[ks & 1];
            #pragma unroll
            for (int mf = 0; mf < 4; mf++)
                #pragma unroll
                for (int nf = 0; nf < 8; nf++)
                    mma_f16(acc[mf][nf], ac[mf], &bc[nf >> 1][(nf & 1) * 2]);
        }
    }

    // ---- epilogue ----
    const int crow = by * 128 + warp_m + (lane >> 2);
    const int ccol = bx * 128 + warp_n + ((lane & 3) << 1);
    #pragma unroll
    for (int mf = 0; mf < 4; mf++) {
        #pragma unroll
        for (int nf = 0; nf < 8; nf++) {
            st2(C + (size_t)(crow + mf * 16)     * ldc + ccol + nf * 8,
                acc[mf][nf][0] * alpha, acc[mf][nf][1] * alpha);
            st2(C + (size_t)(crow + mf * 16 + 8) * ldc + ccol + nf * 8,
                acc[mf][nf][2] * alpha, acc[mf][nf][3] * alpha);
        }
    }
}

// ---------------------------------------------------------------------------
// Row softmax over fp16 S[SEQ][SEQ], in place. One block per row, 256 threads.
// ---------------------------------------------------------------------------
__global__ __launch_bounds__(256)
void softmax_h(__half* __restrict__ S)
{
    constexpr int T = 256;
    constexpr int NV = SEQ / 2 / T;      // 8 half2 per thread
    __shared__ float red[8];
    __shared__ float bcast;

    const int tid = threadIdx.x;
    __half2* p = (__half2*)(S + (size_t)blockIdx.x * SEQ);

    float2 v[NV];
    float mx = -INFINITY;
    #pragma unroll
    for (int i = 0; i < NV; i++) {
        v[i] = __half22float2(p[tid + i * T]);
        mx = fmaxf(mx, fmaxf(v[i].x, v[i].y));
    }
    #pragma unroll
    for (int o = 16; o; o >>= 1) mx = fmaxf(mx, __shfl_xor_sync(0xffffffffu, mx, o));
    if ((tid & 31) == 0) red[tid >> 5] = mx;
    __syncthreads();
    if (tid == 0) {
        float m = red[0];
        #pragma unroll
        for (int i = 1; i < 8; i++) m = fmaxf(m, red[i]);
        bcast = m;
    }
    __syncthreads();
    mx = bcast;

    float sum = 0.f;
    #pragma unroll
    for (int i = 0; i < NV; i++) {
        v[i].x = __expf(v[i].x - mx);
        v[i].y = __expf(v[i].y - mx);
        sum += v[i].x + v[i].y;
    }
    #pragma unroll
    for (int o = 16; o; o >>= 1) sum += __shfl_xor_sync(0xffffffffu, sum, o);
    __syncthreads();
    if ((tid & 31) == 0) red[tid >> 5] = sum;
    __syncthreads();
    if (tid == 0) {
        float s = 0.f;
        #pragma unroll
        for (int i = 0; i < 8; i++) s += red[i];
        bcast = 1.f / s;
    }
    __syncthreads();
    const float inv = bcast;

    #pragma unroll
    for (int i = 0; i < NV; i++)
        p[tid + i * T] = __floats2half2_rn(v[i].x * inv, v[i].y * inv);
}

// ---------------------------------------------------------------------------
extern "C" void kernel_launch(void* const* d_in, const int* in_sizes, int n_in,
                              void* d_out, int out_size)
{
    const float* E  = (const float*)d_in[0];
    const float* Wq = (const float*)d_in[1];
    const float* Wk = (const float*)d_in[2];
    const float* Wv = (const float*)d_in[3];
    float* out = (float*)d_out;

    __half *Eh, *Wh, *QKVh, *Vth, *Sh;
    cudaGetSymbolAddress((void**)&Eh,   g_Eh);
    cudaGetSymbolAddress((void**)&Wh,   g_Wh);
    cudaGetSymbolAddress((void**)&QKVh, g_QKVh);
    cudaGetSymbolAddress((void**)&Vth,  g_Vth);
    cudaGetSymbolAddress((void**)&Sh,   g_Sh);

    constexpr int SMEM_BYTES = 3 * 32768;   // 98304
    cudaFuncSetAttribute(hgemm<__half>,
                         cudaFuncAttributeMaxDynamicSharedMemorySize, SMEM_BYTES);
    cudaFuncSetAttribute(hgemm<float>,
                         cudaFuncAttributeMaxDynamicSharedMemorySize, SMEM_BYTES);

    // prepass: E -> fp16; Wq|Wk|Wv -> transposed fp16 band
    f2h_e<<<dim3(1024, 1, 4), 256>>>(E, Eh);
    transpose_w3<<<dim3(32, 32, 3), 256>>>(Wq, Wk, Wv, Wh);

    dim3 blk(128);

    // QKV: [4096,3072] = E @ Wh^T (NT), fp16 out
    hgemm<__half><<<dim3(DQKV / 128, SEQ / 128), blk, SMEM_BYTES>>>(
        Eh, DMODEL, Wh, DMODEL, QKVh, DQKV, DMODEL, 1.0f);

    const __half* Q  = QKVh;
    const __half* Kp = QKVh + DMODEL;
    const __half* V  = QKVh + 2 * DMODEL;

    // V^T: [1024,4096] fp16
    transpose_h<<<dim3(DMODEL / 32, SEQ / 32), 256>>>(V, DQKV, Vth, SEQ);

    // S = (Q @ K^T) / 32 (NT), fp16 out
    hgemm<__half><<<dim3(SEQ / 128, SEQ / 128), blk, SMEM_BYTES>>>(
        Q, DQKV, Kp, DQKV, Sh, SEQ, DMODEL, 0.03125f);

    // softmax in place (fp16)
    softmax_h<<<SEQ, 256>>>(Sh);

    // out = P @ Vt^T (NT), fp32 out
    hgemm<float><<<dim3(DMODEL / 128, SEQ / 128), blk, SMEM_BYTES>>>(
        Sh, SEQ, Vth, SEQ, out, DMODEL, SEQ, 1.0f);
}